// round 1
// baseline (speedup 1.0000x reference)
#include <cuda_runtime.h>
#include <math.h>
#include <float.h>

// Problem constants
#define B_GR   16
#define NP_    1024
#define FEAT_  512
#define HDIM   1024
#define E_TOT  262144        // 16*1024*16
#define NMAX   16384
#define K1_    820           // ceil(0.8*1024)
#define K2_    656           // ceil(0.8*820)
#define K3_    525           // ceil(0.8*656)

// ---------------- device scratch (no allocation allowed) ----------------
__device__ __align__(16) float g_agg [NMAX * HDIM];   // mean-aggregated features
__device__ __align__(16) float g_bufA[NMAX * HDIM];   // SAGE output (post-relu)
__device__ __align__(16) float g_bufB[NMAX * HDIM];   // pooled/gated features
__device__ int   g_src[E_TOT], g_dst[E_TOT], g_valid[E_TOT], g_csr[E_TOT];
__device__ int   g_cnt[NMAX], g_rowptr[NMAX], g_cursor[NMAX];
__device__ int   g_old[NMAX];
__device__ float g_vals[NMAX];
__device__ int   g_remap[NMAX];
__device__ float g_score[NMAX];
__device__ float g_pnorm;

// ---------------- small utility kernels ----------------
__global__ void edge_init_kernel(const int* __restrict__ ei) {
    int e = blockIdx.x * 256 + threadIdx.x;
    g_src[e] = ei[e];
    g_dst[e] = ei[E_TOT + e];
    g_valid[e] = 1;
}

__global__ void zero_cnt_kernel() {
    int i = blockIdx.x * 256 + threadIdx.x;
    if (i < NMAX) g_cnt[i] = 0;
}

__global__ void zero_out_kernel(float* out) {
    int i = blockIdx.x * 256 + threadIdx.x;
    out[i] = 0.0f;
}

__global__ void count_kernel() {
    int e = blockIdx.x * 256 + threadIdx.x;
    if (g_valid[e]) atomicAdd(&g_cnt[g_dst[e]], 1);
}

// single-block exclusive scan over g_cnt[0..n) -> g_rowptr / g_cursor
__global__ void scan_kernel(int n) {
    __shared__ int part[256];
    int tid = threadIdx.x;
    int chunk = (n + 255) >> 8;
    int base = tid * chunk;
    int s = 0;
    for (int i = 0; i < chunk; i++) { int idx = base + i; if (idx < n) s += g_cnt[idx]; }
    part[tid] = s;
    __syncthreads();
    for (int off = 1; off < 256; off <<= 1) {
        int v = (tid >= off) ? part[tid - off] : 0;
        __syncthreads();
        part[tid] += v;
        __syncthreads();
    }
    int run = part[tid] - s;  // exclusive prefix
    for (int i = 0; i < chunk; i++) {
        int idx = base + i;
        if (idx < n) { g_rowptr[idx] = run; g_cursor[idx] = run; run += g_cnt[idx]; }
    }
}

__global__ void scatter_kernel() {
    int e = blockIdx.x * 256 + threadIdx.x;
    if (g_valid[e]) {
        int pos = atomicAdd(&g_cursor[g_dst[e]], 1);
        g_csr[pos] = g_src[e];
    }
}

// one block (256 threads) per dst node; NF = F/256
template <int NF>
__global__ void aggregate_kernel(const float* __restrict__ xext, int sel, int F) {
    const float* __restrict__ xin = sel ? g_bufB : xext;
    int node = blockIdx.x;
    int c = g_cnt[node];
    int start = g_rowptr[node];
    float acc[NF];
#pragma unroll
    for (int i = 0; i < NF; i++) acc[i] = 0.0f;
    for (int e = 0; e < c; e++) {
        const float* row = xin + (size_t)g_csr[start + e] * F;
#pragma unroll
        for (int i = 0; i < NF; i++) acc[i] += row[threadIdx.x + i * 256];
    }
    float inv = 1.0f / (float)(c > 1 ? c : 1);
#pragma unroll
    for (int i = 0; i < NF; i++)
        g_agg[(size_t)node * F + threadIdx.x + i * 256] = acc[i] * inv;
}

// ---------------- fused SAGE GEMM ----------------
// C[N,1024] = relu( mean @ Wl^T + b + X @ Wr^T )
// A1 = g_agg (mean), A2 = x (sel==0 -> external ptr, else g_bufB). All row-major [*,K].
// BM=64 (N divisible by 64), BN=128, BK=16, 128 threads, 8x8 per thread.
__global__ void __launch_bounds__(128)
gemm_kernel(const float* __restrict__ xext, int a2sel,
            const float* __restrict__ Wl, const float* __restrict__ Wr,
            const float* __restrict__ bias, int N, int K) {
    const float* __restrict__ A1 = g_agg;
    const float* __restrict__ A2 = a2sel ? g_bufB : xext;
    float* __restrict__ C = g_bufA;

    __shared__ float As[16][64];
    __shared__ float Bs[16][128];

    int tid = threadIdx.x;
    int tm = tid >> 4;    // 0..7  (8 rows each)
    int tn = tid & 15;    // 0..15 (8 cols each)
    int row0 = blockIdx.x * 64;
    int col0 = blockIdx.y * 128;

    float acc[8][8];
#pragma unroll
    for (int i = 0; i < 8; i++)
#pragma unroll
        for (int j = 0; j < 8; j++) acc[i][j] = 0.0f;

    int ktiles = K >> 4;
    for (int t = 0; t < 2 * ktiles; ++t) {
        const float* A = (t < ktiles) ? A1 : A2;
        const float* W = (t < ktiles) ? Wl : Wr;
        int k0 = ((t < ktiles) ? t : (t - ktiles)) << 4;

        // A tile: 64x16 = 256 float4
#pragma unroll
        for (int i = 0; i < 2; ++i) {
            int q = tid + i * 128;
            int r = q >> 2;
            int kq = (q & 3) << 2;
            float4 v = *(const float4*)(A + (size_t)(row0 + r) * K + k0 + kq);
            As[kq + 0][r] = v.x; As[kq + 1][r] = v.y;
            As[kq + 2][r] = v.z; As[kq + 3][r] = v.w;
        }
        // B tile: 128x16 = 512 float4
#pragma unroll
        for (int i = 0; i < 4; ++i) {
            int q = tid + i * 128;
            int r = q >> 2;
            int kq = (q & 3) << 2;
            float4 v = *(const float4*)(W + (size_t)(col0 + r) * K + k0 + kq);
            Bs[kq + 0][r] = v.x; Bs[kq + 1][r] = v.y;
            Bs[kq + 2][r] = v.z; Bs[kq + 3][r] = v.w;
        }
        __syncthreads();

#pragma unroll
        for (int k = 0; k < 16; ++k) {
            float a[8], b[8];
#pragma unroll
            for (int i = 0; i < 8; i++) a[i] = As[k][tm * 8 + i];
#pragma unroll
            for (int j = 0; j < 8; j++) b[j] = Bs[k][tn * 8 + j];
#pragma unroll
            for (int i = 0; i < 8; i++)
#pragma unroll
                for (int j = 0; j < 8; j++) acc[i][j] += a[i] * b[j];
        }
        __syncthreads();
    }

#pragma unroll
    for (int i = 0; i < 8; i++) {
        int r = row0 + tm * 8 + i;
#pragma unroll
        for (int j = 0; j < 8; j++) {
            int c = col0 + tn * 8 + j;
            float v = acc[i][j] + bias[c];
            C[(size_t)r * HDIM + c] = fmaxf(v, 0.0f);
        }
    }
}

// ---------------- scoring / top-k / pooling ----------------
__global__ void pnorm_kernel(const float* __restrict__ p) {
    __shared__ float sh[256];
    float s = 0.0f;
    for (int i = threadIdx.x; i < HDIM; i += 256) s += p[i] * p[i];
    sh[threadIdx.x] = s;
    __syncthreads();
    for (int o = 128; o; o >>= 1) {
        if (threadIdx.x < o) sh[threadIdx.x] += sh[threadIdx.x + o];
        __syncthreads();
    }
    if (threadIdx.x == 0) g_pnorm = sqrtf(sh[0]);
}

// one warp per node: s = tanh((h . p)/||p||)
__global__ void score_kernel(const float* __restrict__ p, int N) {
    int t = blockIdx.x * blockDim.x + threadIdx.x;
    int warp = t >> 5, lane = t & 31;
    if (warp >= N) return;
    const float* row = g_bufA + (size_t)warp * HDIM;
    float acc = 0.0f;
#pragma unroll 8
    for (int i = lane; i < HDIM; i += 32) acc += row[i] * p[i];
#pragma unroll
    for (int o = 16; o; o >>= 1) acc += __shfl_xor_sync(0xffffffffu, acc, o);
    if (lane == 0) g_score[warp] = tanhf(acc / g_pnorm);
}

// one block per graph: bitonic sort 1024 (score,idx) pairs descending
__global__ void topk_kernel(int n_per, int k) {
    __shared__ float ss[1024];
    __shared__ int si[1024];
    int g = blockIdx.x;
    int tid = threadIdx.x;  // 512 threads
    for (int i = tid; i < 1024; i += 512) {
        if (i < n_per) { ss[i] = g_score[g * n_per + i]; si[i] = i; }
        else           { ss[i] = -FLT_MAX;               si[i] = i; }
    }
    __syncthreads();
    for (int ksz = 2; ksz <= 1024; ksz <<= 1) {
        for (int j = ksz >> 1; j > 0; j >>= 1) {
            for (int i = tid; i < 1024; i += 512) {
                int ixj = i ^ j;
                if (ixj > i) {
                    bool dirDesc = ((i & ksz) == 0);
                    float a = ss[i], b = ss[ixj];
                    bool doswap = dirDesc ? (a < b) : (a > b);
                    if (doswap) {
                        ss[i] = b; ss[ixj] = a;
                        int tpi = si[i]; si[i] = si[ixj]; si[ixj] = tpi;
                    }
                }
            }
            __syncthreads();
        }
    }
    for (int r = tid; r < n_per; r += 512) {
        int oldLocal = si[r];
        if (r < k) {
            g_old[g * k + r]  = g * n_per + oldLocal;
            g_vals[g * k + r] = ss[r];
            g_remap[g * n_per + oldLocal] = g * k + r;
        } else {
            g_remap[g * n_per + oldLocal] = -1;
        }
    }
}

// new node i <- old node * score
__global__ void gate_kernel() {
    int i = blockIdx.x;
    int old = g_old[i];
    float v = g_vals[i];
    const float* srcp = g_bufA + (size_t)old * HDIM;
    float* dstp = g_bufB + (size_t)i * HDIM;
    for (int f = threadIdx.x; f < HDIM; f += 256) dstp[f] = srcp[f] * v;
}

__global__ void edge_remap_kernel() {
    int e = blockIdx.x * 256 + threadIdx.x;
    if (!g_valid[e]) return;
    int s2 = g_remap[g_src[e]];
    int d2 = g_remap[g_dst[e]];
    if (s2 >= 0 && d2 >= 0) { g_src[e] = s2; g_dst[e] = d2; }
    else g_valid[e] = 0;
}

// out[g, 0:1024] += col-max, out[g, 1024:2048] += col-mean   (over bufB)
__global__ void readout_kernel(float* __restrict__ out, int nper) {
    int gid = blockIdx.x * 256 + threadIdx.x;  // < B*1024
    int g = gid >> 10, f = gid & 1023;
    const float* base = g_bufB + (size_t)g * nper * HDIM + f;
    float mx = -FLT_MAX, sm = 0.0f;
    for (int i = 0; i < nper; i++) {
        float v = base[(size_t)i * HDIM];
        mx = fmaxf(mx, v);
        sm += v;
    }
    out[g * 2048 + f] += mx;
    out[g * 2048 + 1024 + f] += sm / (float)nper;
}

// ---------------- host orchestration ----------------
static void build_csr(int n_nodes) {
    zero_cnt_kernel<<<NMAX / 256, 256>>>();
    count_kernel<<<E_TOT / 256, 256>>>();
    scan_kernel<<<1, 256>>>(n_nodes);
    scatter_kernel<<<E_TOT / 256, 256>>>();
}

extern "C" void kernel_launch(void* const* d_in, const int* in_sizes, int n_in,
                              void* d_out, int out_size) {
    const float* x  = (const float*)d_in[0];
    const int*   ei = (const int*)d_in[1];
    const float* W1l = (const float*)d_in[3];
    const float* b1  = (const float*)d_in[4];
    const float* W1r = (const float*)d_in[5];
    const float* p1  = (const float*)d_in[6];
    const float* W2l = (const float*)d_in[7];
    const float* b2  = (const float*)d_in[8];
    const float* W2r = (const float*)d_in[9];
    const float* p2  = (const float*)d_in[10];
    const float* W3l = (const float*)d_in[11];
    const float* b3  = (const float*)d_in[12];
    const float* W3r = (const float*)d_in[13];
    const float* p3  = (const float*)d_in[14];
    float* out = (float*)d_out;

    const int N1 = B_GR * NP_;   // 16384
    const int N2 = B_GR * K1_;   // 13120
    const int N3 = B_GR * K2_;   // 10496

    edge_init_kernel<<<E_TOT / 256, 256>>>(ei);
    zero_out_kernel<<<(B_GR * 2 * HDIM) / 256, 256>>>(out);

    // ---------- layer 1 ----------
    build_csr(N1);
    aggregate_kernel<2><<<N1, 256>>>(x, 0, FEAT_);
    gemm_kernel<<<dim3(N1 / 64, HDIM / 128), 128>>>(x, 0, W1l, W1r, b1, N1, FEAT_);
    pnorm_kernel<<<1, 256>>>(p1);
    score_kernel<<<N1 / 8, 256>>>(p1, N1);
    topk_kernel<<<B_GR, 512>>>(NP_, K1_);
    gate_kernel<<<N2, 256>>>();
    edge_remap_kernel<<<E_TOT / 256, 256>>>();
    readout_kernel<<<(B_GR * HDIM) / 256, 256>>>(out, K1_);

    // ---------- layer 2 ----------
    build_csr(N2);
    aggregate_kernel<4><<<N2, 256>>>(nullptr, 1, HDIM);
    gemm_kernel<<<dim3(N2 / 64, HDIM / 128), 128>>>(nullptr, 1, W2l, W2r, b2, N2, HDIM);
    pnorm_kernel<<<1, 256>>>(p2);
    score_kernel<<<N2 / 8, 256>>>(p2, N2);
    topk_kernel<<<B_GR, 512>>>(K1_, K2_);
    gate_kernel<<<N3, 256>>>();
    edge_remap_kernel<<<E_TOT / 256, 256>>>();
    readout_kernel<<<(B_GR * HDIM) / 256, 256>>>(out, K2_);

    // ---------- layer 3 ----------
    build_csr(N3);
    aggregate_kernel<4><<<N3, 256>>>(nullptr, 1, HDIM);
    gemm_kernel<<<dim3(N3 / 64, HDIM / 128), 128>>>(nullptr, 1, W3l, W3r, b3, N3, HDIM);
    pnorm_kernel<<<1, 256>>>(p3);
    score_kernel<<<N3 / 8, 256>>>(p3, N3);
    topk_kernel<<<B_GR, 512>>>(K2_, K3_);
    gate_kernel<<<B_GR * K3_, 256>>>();
    // final edge remap unnecessary (edges unused after last pool)
    readout_kernel<<<(B_GR * HDIM) / 256, 256>>>(out, K3_);
}

// round 3
// speedup vs baseline: 2.2471x; 2.2471x over previous
#include <cuda_runtime.h>
#include <cuda_bf16.h>
#include <math.h>
#include <float.h>
#include <stdint.h>

// Problem constants
#define B_GR   16
#define NP_    1024
#define FEAT_  512
#define HDIM   1024
#define E_TOT  262144        // 16*1024*16
#define NMAX   16384
#define K1_    820           // ceil(0.8*1024)
#define K2_    656           // ceil(0.8*820)
#define K3_    525           // ceil(0.8*656)

// ---------------- device scratch (no allocation allowed) ----------------
__device__ __align__(16) float g_bufA[NMAX * HDIM];   // SAGE output (post-relu)
__device__ __align__(16) float g_bufB[NMAX * HDIM];   // pooled/gated features (fp32)
// bf16 split operand buffers for the MMA GEMM
__device__ __align__(16) __nv_bfloat16 g_ahi[NMAX * HDIM];   // mean-agg hi
__device__ __align__(16) __nv_bfloat16 g_alo[NMAX * HDIM];   // mean-agg lo
__device__ __align__(16) __nv_bfloat16 g_xhi[NMAX * HDIM];   // x / pooled hi
__device__ __align__(16) __nv_bfloat16 g_xlo[NMAX * HDIM];   // x / pooled lo
__device__ __align__(16) __nv_bfloat16 g_whi[2 * HDIM * HDIM];  // [Wl ; Wr] hi
__device__ __align__(16) __nv_bfloat16 g_wlo[2 * HDIM * HDIM];  // [Wl ; Wr] lo

__device__ int   g_src[E_TOT], g_dst[E_TOT], g_valid[E_TOT], g_csr[E_TOT];
__device__ int   g_cnt[NMAX], g_rowptr[NMAX], g_cursor[NMAX];
__device__ int   g_old[NMAX];
__device__ float g_vals[NMAX];
__device__ int   g_remap[NMAX];
__device__ float g_score[NMAX];
__device__ float g_pnorm;

// ---------------- PTX helpers (all sm_80-level, no arch-variant features) --
static __device__ __forceinline__ uint32_t smem_u32(const void* p) {
    uint32_t a;
    asm("{ .reg .u64 t; cvta.to.shared.u64 t, %1; cvt.u32.u64 %0, t; }"
        : "=r"(a) : "l"(p));
    return a;
}

__device__ __forceinline__ void cpa16(uint32_t dst, const void* src, int szbytes) {
    asm volatile("cp.async.cg.shared.global [%0], [%1], 16, %2;"
                 :: "r"(dst), "l"(src), "r"(szbytes));
}
#define CP_COMMIT() asm volatile("cp.async.commit_group;" ::: "memory")
#define CP_WAIT1()  asm volatile("cp.async.wait_group 1;" ::: "memory")

#define LDSM_X4(R, addr) \
    asm volatile("ldmatrix.sync.aligned.m8n8.x4.shared.b16 {%0,%1,%2,%3}, [%4];" \
        : "=r"((R)[0]), "=r"((R)[1]), "=r"((R)[2]), "=r"((R)[3]) : "r"(addr))

#define MMA16816(C, A, B0, B1) \
    asm volatile("mma.sync.aligned.m16n8k16.row.col.f32.bf16.bf16.f32 " \
        "{%0,%1,%2,%3}, {%4,%5,%6,%7}, {%8,%9}, {%0,%1,%2,%3};" \
        : "+f"((C)[0]), "+f"((C)[1]), "+f"((C)[2]), "+f"((C)[3]) \
        : "r"((A)[0]), "r"((A)[1]), "r"((A)[2]), "r"((A)[3]), "r"(B0), "r"(B1))

// swizzled byte offset inside a tile with 64B (32 bf16) rows
__device__ __forceinline__ uint32_t sw64(int r, int c) {
    return (uint32_t)(r * 64 + ((c ^ ((r >> 1) & 3)) << 4));
}

// ---------------- GEMM smem layout ----------------
#define S_AH 0
#define S_AL 8192
#define S_BH 16384
#define S_BL 24576
#define STAGE_SZ 32768
#define GEMM_SMEM (3 * STAGE_SZ)   // 96 KB, 3-stage ring

// ---------------- small utility kernels ----------------
__global__ void edge_init_kernel(const int* __restrict__ ei) {
    int e = blockIdx.x * 256 + threadIdx.x;
    g_src[e] = ei[e];
    g_dst[e] = ei[E_TOT + e];
    g_valid[e] = 1;
}

__global__ void zero_cnt_kernel() {
    int i = blockIdx.x * 256 + threadIdx.x;
    if (i < NMAX) g_cnt[i] = 0;
}

__global__ void zero_out_kernel(float* out) {
    int i = blockIdx.x * 256 + threadIdx.x;
    out[i] = 0.0f;
}

__global__ void count_kernel() {
    int e = blockIdx.x * 256 + threadIdx.x;
    if (g_valid[e]) atomicAdd(&g_cnt[g_dst[e]], 1);
}

// single-block exclusive scan over g_cnt[0..n) -> g_rowptr / g_cursor
__global__ void scan_kernel(int n) {
    __shared__ int part[256];
    int tid = threadIdx.x;
    int chunk = (n + 255) >> 8;
    int base = tid * chunk;
    int s = 0;
    for (int i = 0; i < chunk; i++) { int idx = base + i; if (idx < n) s += g_cnt[idx]; }
    part[tid] = s;
    __syncthreads();
    for (int off = 1; off < 256; off <<= 1) {
        int v = (tid >= off) ? part[tid - off] : 0;
        __syncthreads();
        part[tid] += v;
        __syncthreads();
    }
    int run = part[tid] - s;  // exclusive prefix
    for (int i = 0; i < chunk; i++) {
        int idx = base + i;
        if (idx < n) { g_rowptr[idx] = run; g_cursor[idx] = run; run += g_cnt[idx]; }
    }
}

__global__ void scatter_kernel() {
    int e = blockIdx.x * 256 + threadIdx.x;
    if (g_valid[e]) {
        int pos = atomicAdd(&g_cursor[g_dst[e]], 1);
        g_csr[pos] = g_src[e];
    }
}

__device__ __forceinline__ void split_store(float v, __nv_bfloat16* hi, __nv_bfloat16* lo) {
    __nv_bfloat16 h = __float2bfloat16(v);
    *hi = h;
    *lo = __float2bfloat16(v - __bfloat162float(h));
}

// one block (256 threads) per dst node; NF = F/256. Writes bf16 hi/lo directly.
template <int NF>
__global__ void aggregate_kernel(const float* __restrict__ xext, int sel, int F) {
    const float* __restrict__ xin = sel ? g_bufB : xext;
    int node = blockIdx.x;
    int c = g_cnt[node];
    int start = g_rowptr[node];
    float acc[NF];
#pragma unroll
    for (int i = 0; i < NF; i++) acc[i] = 0.0f;
    for (int e = 0; e < c; e++) {
        const float* row = xin + (size_t)g_csr[start + e] * F;
#pragma unroll
        for (int i = 0; i < NF; i++) acc[i] += row[threadIdx.x + i * 256];
    }
    float inv = 1.0f / (float)(c > 1 ? c : 1);
#pragma unroll
    for (int i = 0; i < NF; i++) {
        size_t o = (size_t)node * F + threadIdx.x + i * 256;
        split_store(acc[i] * inv, &g_ahi[o], &g_alo[o]);
    }
}

// fp32 -> bf16 hi/lo conversion (for x input and weights)
__global__ void conv_kernel(const float* __restrict__ src,
                            __nv_bfloat16* __restrict__ hi,
                            __nv_bfloat16* __restrict__ lo, int n) {
    int i = blockIdx.x * 256 + threadIdx.x;
    if (i < n) split_store(src[i], &hi[i], &lo[i]);
}

// ---------------- mma.sync fused SAGE GEMM ----------------
// g_bufA[M,1024] = relu( Agg @ Wl^T + bias + X @ Wr^T )
// 3-term bf16 split per operand pair: Ah*Bh + Ah*Bl + Al*Bh, fp32 accum.
// CTA tile 128x128, BK=32, 8 warps (warp tile 32m x 64n), cp.async 3-stage ring.
__global__ void __launch_bounds__(256, 1)
gemm_mma_kernel(int M, int K, const float* __restrict__ bias) {
    extern __shared__ char smem[];
    const uint32_t sbase = smem_u32(smem);
    const int tid  = threadIdx.x;
    const int lane = tid & 31;
    const int warp = tid >> 5;
    const int warpM = (warp & 3) * 32;
    const int warpN = (warp >> 2) * 64;
    const int row0 = blockIdx.x << 7;
    const int col0 = blockIdx.y << 7;

    const int nchunk = K >> 5;       // k32 chunks per operand source
    const int ntot = nchunk << 1;

    float C[2][8][4];
#pragma unroll
    for (int a = 0; a < 2; a++)
#pragma unroll
        for (int b = 0; b < 8; b++)
#pragma unroll
            for (int d = 0; d < 4; d++) C[a][b][d] = 0.0f;

    // ---- stage prefetch (always commits exactly one group) ----
    auto prefetch = [&](int i) {
        if (i < ntot) {
            int src = (i >= nchunk) ? 1 : 0;
            int k0 = (i - (src ? nchunk : 0)) << 5;
            const __nv_bfloat16* Ah = src ? g_xhi : g_ahi;
            const __nv_bfloat16* Al = src ? g_xlo : g_alo;
            const __nv_bfloat16* Bh = g_whi + (size_t)src * HDIM * K;
            const __nv_bfloat16* Bl = g_wlo + (size_t)src * HDIM * K;
            uint32_t sb = sbase + (uint32_t)(i % 3) * STAGE_SZ;
#pragma unroll
            for (int u = 0; u < 2; u++) {
                int q = tid + (u << 8);
                int r = q >> 2, c = q & 3;
                uint32_t so = sw64(r, c);
                int gr = row0 + r;
                int ok = (gr < M) ? 16 : 0;
                size_t gro = (size_t)(ok ? gr : 0) * K + k0 + (c << 3);
                cpa16(sb + S_AH + so, Ah + gro, ok);
                cpa16(sb + S_AL + so, Al + gro, ok);
                size_t gco = (size_t)(col0 + r) * K + k0 + (c << 3);
                cpa16(sb + S_BH + so, Bh + gco, 16);
                cpa16(sb + S_BL + so, Bl + gco, 16);
            }
        }
        CP_COMMIT();
    };

    prefetch(0);
    prefetch(1);

    for (int i = 0; i < ntot; i++) {
        CP_WAIT1();
        __syncthreads();
        prefetch(i + 2);

        uint32_t sb = sbase + (uint32_t)(i % 3) * STAGE_SZ;
#pragma unroll
        for (int kk = 0; kk < 2; kk++) {
            uint32_t ah[2][4], al[2][4];
#pragma unroll
            for (int fm = 0; fm < 2; fm++) {
                int r = warpM + fm * 16 + (lane & 15);
                int c = (kk << 1) + (lane >> 4);
                uint32_t so = sw64(r, c);
                LDSM_X4(ah[fm], sb + S_AH + so);
                LDSM_X4(al[fm], sb + S_AL + so);
            }
            uint32_t bh[4][4], bl[4][4];
#pragma unroll
            for (int fn = 0; fn < 4; fn++) {
                int r = warpN + fn * 16 + ((lane >> 4) << 3) + (lane & 7);
                int c = (kk << 1) + ((lane >> 3) & 1);
                uint32_t so = sw64(r, c);
                LDSM_X4(bh[fn], sb + S_BH + so);
                LDSM_X4(bl[fn], sb + S_BL + so);
            }
#pragma unroll
            for (int fm = 0; fm < 2; fm++)
#pragma unroll
                for (int fn = 0; fn < 4; fn++)
#pragma unroll
                    for (int g = 0; g < 2; g++) {
                        float* Cp = C[fm][fn * 2 + g];
                        MMA16816(Cp, ah[fm], bh[fn][g * 2], bh[fn][g * 2 + 1]);
                        MMA16816(Cp, ah[fm], bl[fn][g * 2], bl[fn][g * 2 + 1]);
                        MMA16816(Cp, al[fm], bh[fn][g * 2], bh[fn][g * 2 + 1]);
                    }
        }
        __syncthreads();
    }

    // ---- epilogue: bias + relu, direct stores ----
#pragma unroll
    for (int fm = 0; fm < 2; fm++)
#pragma unroll
        for (int fn = 0; fn < 4; fn++)
#pragma unroll
            for (int g = 0; g < 2; g++) {
                int rb = row0 + warpM + fm * 16 + (lane >> 2);
                int col = col0 + warpN + fn * 16 + g * 8 + ((lane & 3) << 1);
                float2 bb = *(const float2*)(bias + col);
                float* Cp = C[fm][fn * 2 + g];
                if (rb < M) {
                    float2 v;
                    v.x = fmaxf(Cp[0] + bb.x, 0.0f);
                    v.y = fmaxf(Cp[1] + bb.y, 0.0f);
                    *(float2*)(g_bufA + (size_t)rb * HDIM + col) = v;
                }
                if (rb + 8 < M) {
                    float2 v;
                    v.x = fmaxf(Cp[2] + bb.x, 0.0f);
                    v.y = fmaxf(Cp[3] + bb.y, 0.0f);
                    *(float2*)(g_bufA + (size_t)(rb + 8) * HDIM + col) = v;
                }
            }
}

// ---------------- scoring / top-k / pooling ----------------
__global__ void pnorm_kernel(const float* __restrict__ p) {
    __shared__ float sh[256];
    float s = 0.0f;
    for (int i = threadIdx.x; i < HDIM; i += 256) s += p[i] * p[i];
    sh[threadIdx.x] = s;
    __syncthreads();
    for (int o = 128; o; o >>= 1) {
        if (threadIdx.x < o) sh[threadIdx.x] += sh[threadIdx.x + o];
        __syncthreads();
    }
    if (threadIdx.x == 0) g_pnorm = sqrtf(sh[0]);
}

// one warp per node: s = tanh((h . p)/||p||)
__global__ void score_kernel(const float* __restrict__ p, int N) {
    int t = blockIdx.x * blockDim.x + threadIdx.x;
    int warp = t >> 5, lane = t & 31;
    if (warp >= N) return;
    const float* row = g_bufA + (size_t)warp * HDIM;
    float acc = 0.0f;
#pragma unroll 8
    for (int i = lane; i < HDIM; i += 32) acc += row[i] * p[i];
#pragma unroll
    for (int o = 16; o; o >>= 1) acc += __shfl_xor_sync(0xffffffffu, acc, o);
    if (lane == 0) g_score[warp] = tanhf(acc / g_pnorm);
}

// one block per graph: bitonic sort 1024 (score,idx) pairs descending
__global__ void topk_kernel(int n_per, int k) {
    __shared__ float ss[1024];
    __shared__ int si[1024];
    int g = blockIdx.x;
    int tid = threadIdx.x;  // 512 threads
    for (int i = tid; i < 1024; i += 512) {
        if (i < n_per) { ss[i] = g_score[g * n_per + i]; si[i] = i; }
        else           { ss[i] = -FLT_MAX;               si[i] = i; }
    }
    __syncthreads();
    for (int ksz = 2; ksz <= 1024; ksz <<= 1) {
        for (int j = ksz >> 1; j > 0; j >>= 1) {
            for (int i = tid; i < 1024; i += 512) {
                int ixj = i ^ j;
                if (ixj > i) {
                    bool dirDesc = ((i & ksz) == 0);
                    float a = ss[i], b = ss[ixj];
                    bool doswap = dirDesc ? (a < b) : (a > b);
                    if (doswap) {
                        ss[i] = b; ss[ixj] = a;
                        int tpi = si[i]; si[i] = si[ixj]; si[ixj] = tpi;
                    }
                }
            }
            __syncthreads();
        }
    }
    for (int r = tid; r < n_per; r += 512) {
        int oldLocal = si[r];
        if (r < k) {
            g_old[g * k + r]  = g * n_per + oldLocal;
            g_vals[g * k + r] = ss[r];
            g_remap[g * n_per + oldLocal] = g * k + r;
        } else {
            g_remap[g * n_per + oldLocal] = -1;
        }
    }
}

// new node i <- old node * score; also emit bf16 hi/lo for the next layer GEMM
__global__ void gate_kernel() {
    int i = blockIdx.x;
    int old = g_old[i];
    float v = g_vals[i];
    const float* srcp = g_bufA + (size_t)old * HDIM;
    float* dstp = g_bufB + (size_t)i * HDIM;
    for (int f = threadIdx.x; f < HDIM; f += 256) {
        float val = srcp[f] * v;
        dstp[f] = val;
        split_store(val, &g_xhi[(size_t)i * HDIM + f], &g_xlo[(size_t)i * HDIM + f]);
    }
}

__global__ void edge_remap_kernel() {
    int e = blockIdx.x * 256 + threadIdx.x;
    if (!g_valid[e]) return;
    int s2 = g_remap[g_src[e]];
    int d2 = g_remap[g_dst[e]];
    if (s2 >= 0 && d2 >= 0) { g_src[e] = s2; g_dst[e] = d2; }
    else g_valid[e] = 0;
}

// out[g, 0:1024] += col-max, out[g, 1024:2048] += col-mean   (over bufB)
__global__ void readout_kernel(float* __restrict__ out, int nper) {
    int gid = blockIdx.x * 256 + threadIdx.x;  // < B*1024
    int g = gid >> 10, f = gid & 1023;
    const float* base = g_bufB + (size_t)g * nper * HDIM + f;
    float mx = -FLT_MAX, sm = 0.0f;
    for (int i = 0; i < nper; i++) {
        float v = base[(size_t)i * HDIM];
        mx = fmaxf(mx, v);
        sm += v;
    }
    out[g * 2048 + f] += mx;
    out[g * 2048 + 1024 + f] += sm / (float)nper;
}

// ---------------- host orchestration ----------------
static void build_csr(int n_nodes) {
    zero_cnt_kernel<<<NMAX / 256, 256>>>();
    count_kernel<<<E_TOT / 256, 256>>>();
    scan_kernel<<<1, 256>>>(n_nodes);
    scatter_kernel<<<E_TOT / 256, 256>>>();
}

static void launch_gemm(int M, int K, const float* bias) {
    dim3 grid((M + 127) >> 7, HDIM / 128);
    gemm_mma_kernel<<<grid, 256, GEMM_SMEM>>>(M, K, bias);
}

extern "C" void kernel_launch(void* const* d_in, const int* in_sizes, int n_in,
                              void* d_out, int out_size) {
    const float* x  = (const float*)d_in[0];
    const int*   ei = (const int*)d_in[1];
    const float* W1l = (const float*)d_in[3];
    const float* b1  = (const float*)d_in[4];
    const float* W1r = (const float*)d_in[5];
    const float* p1  = (const float*)d_in[6];
    const float* W2l = (const float*)d_in[7];
    const float* b2  = (const float*)d_in[8];
    const float* W2r = (const float*)d_in[9];
    const float* p2  = (const float*)d_in[10];
    const float* W3l = (const float*)d_in[11];
    const float* b3  = (const float*)d_in[12];
    const float* W3r = (const float*)d_in[13];
    const float* p3  = (const float*)d_in[14];
    float* out = (float*)d_out;

    static int s_attr_done = 0;
    if (!s_attr_done) {
        cudaFuncSetAttribute(gemm_mma_kernel,
                             cudaFuncAttributeMaxDynamicSharedMemorySize, GEMM_SMEM);
        s_attr_done = 1;
    }

    const int N1 = B_GR * NP_;   // 16384
    const int N2 = B_GR * K1_;   // 13120
    const int N3 = B_GR * K2_;   // 10496

    __nv_bfloat16 *whi = nullptr, *wlo = nullptr;
    cudaGetSymbolAddress((void**)&whi, g_whi);
    cudaGetSymbolAddress((void**)&wlo, g_wlo);
    __nv_bfloat16 *xhi = nullptr, *xlo = nullptr;
    cudaGetSymbolAddress((void**)&xhi, g_xhi);
    cudaGetSymbolAddress((void**)&xlo, g_xlo);

    edge_init_kernel<<<E_TOT / 256, 256>>>(ei);
    zero_out_kernel<<<(B_GR * 2 * HDIM) / 256, 256>>>(out);

    // ---------- layer 1 (K = 512) ----------
    build_csr(N1);
    aggregate_kernel<2><<<N1, 256>>>(x, 0, FEAT_);
    conv_kernel<<<(N1 * FEAT_) / 256, 256>>>(x, xhi, xlo, N1 * FEAT_);
    conv_kernel<<<(HDIM * FEAT_) / 256, 256>>>(W1l, whi, wlo, HDIM * FEAT_);
    conv_kernel<<<(HDIM * FEAT_) / 256, 256>>>(W1r, whi + HDIM * FEAT_, wlo + HDIM * FEAT_,
                                               HDIM * FEAT_);
    launch_gemm(N1, FEAT_, b1);
    pnorm_kernel<<<1, 256>>>(p1);
    score_kernel<<<N1 / 8, 256>>>(p1, N1);
    topk_kernel<<<B_GR, 512>>>(NP_, K1_);
    gate_kernel<<<N2, 256>>>();
    edge_remap_kernel<<<E_TOT / 256, 256>>>();
    readout_kernel<<<(B_GR * HDIM) / 256, 256>>>(out, K1_);

    // ---------- layer 2 (K = 1024) ----------
    build_csr(N2);
    aggregate_kernel<4><<<N2, 256>>>(nullptr, 1, HDIM);
    conv_kernel<<<(HDIM * HDIM) / 256, 256>>>(W2l, whi, wlo, HDIM * HDIM);
    conv_kernel<<<(HDIM * HDIM) / 256, 256>>>(W2r, whi + HDIM * HDIM, wlo + HDIM * HDIM,
                                              HDIM * HDIM);
    launch_gemm(N2, HDIM, b2);
    pnorm_kernel<<<1, 256>>>(p2);
    score_kernel<<<N2 / 8, 256>>>(p2, N2);
    topk_kernel<<<B_GR, 512>>>(K1_, K2_);
    gate_kernel<<<N3, 256>>>();
    edge_remap_kernel<<<E_TOT / 256, 256>>>();
    readout_kernel<<<(B_GR * HDIM) / 256, 256>>>(out, K2_);

    // ---------- layer 3 (K = 1024) ----------
    build_csr(N3);
    aggregate_kernel<4><<<N3, 256>>>(nullptr, 1, HDIM);
    conv_kernel<<<(HDIM * HDIM) / 256, 256>>>(W3l, whi, wlo, HDIM * HDIM);
    conv_kernel<<<(HDIM * HDIM) / 256, 256>>>(W3r, whi + HDIM * HDIM, wlo + HDIM * HDIM,
                                              HDIM * HDIM);
    launch_gemm(N3, HDIM, b3);
    pnorm_kernel<<<1, 256>>>(p3);
    score_kernel<<<N3 / 8, 256>>>(p3, N3);
    topk_kernel<<<B_GR, 512>>>(K2_, K3_);
    gate_kernel<<<B_GR * K3_, 256>>>();
    readout_kernel<<<(B_GR * HDIM) / 256, 256>>>(out, K3_);
}

// round 4
// speedup vs baseline: 2.3168x; 1.0311x over previous
#include <cuda_runtime.h>
#include <cuda_bf16.h>
#include <math.h>
#include <float.h>
#include <stdint.h>

// Problem constants
#define B_GR   16
#define NP_    1024
#define FEAT_  512
#define HDIM   1024
#define E_TOT  262144        // 16*1024*16
#define NMAX   16384
#define K1_    820           // ceil(0.8*1024)
#define K2_    656           // ceil(0.8*820)
#define K3_    525           // ceil(0.8*656)

// ---------------- device scratch (no allocation allowed) ----------------
__device__ __align__(16) float g_bufA[NMAX * HDIM];   // SAGE output (post-relu)
__device__ __align__(16) float g_bufB[NMAX * HDIM];   // pooled/gated features (fp32)
// bf16 split operand buffers for the MMA GEMM
__device__ __align__(16) __nv_bfloat16 g_ahi[NMAX * HDIM];   // mean-agg hi
__device__ __align__(16) __nv_bfloat16 g_alo[NMAX * HDIM];   // mean-agg lo
__device__ __align__(16) __nv_bfloat16 g_xhi[NMAX * HDIM];   // x / pooled hi
__device__ __align__(16) __nv_bfloat16 g_xlo[NMAX * HDIM];   // x / pooled lo
__device__ __align__(16) __nv_bfloat16 g_whi[2 * HDIM * HDIM];  // [Wl ; Wr] hi
__device__ __align__(16) __nv_bfloat16 g_wlo[2 * HDIM * HDIM];  // [Wl ; Wr] lo

__device__ int   g_src[E_TOT], g_dst[E_TOT], g_valid[E_TOT], g_csr[E_TOT];
__device__ int   g_cnt[NMAX], g_rowptr[NMAX], g_cursor[NMAX];
__device__ int   g_old[NMAX];
__device__ float g_vals[NMAX];
__device__ int   g_remap[NMAX];
__device__ float g_score[NMAX];
__device__ float g_pnorm;

// ---------------- PTX helpers (all sm_80-level, no arch-variant features) --
static __device__ __forceinline__ uint32_t smem_u32(const void* p) {
    uint32_t a;
    asm("{ .reg .u64 t; cvta.to.shared.u64 t, %1; cvt.u32.u64 %0, t; }"
        : "=r"(a) : "l"(p));
    return a;
}

__device__ __forceinline__ void cpa16(uint32_t dst, const void* src, int szbytes) {
    asm volatile("cp.async.cg.shared.global [%0], [%1], 16, %2;"
                 :: "r"(dst), "l"(src), "r"(szbytes));
}
#define CP_COMMIT() asm volatile("cp.async.commit_group;" ::: "memory")
#define CP_WAIT2()  asm volatile("cp.async.wait_group 2;" ::: "memory")

#define LDSM_X4(R, addr) \
    asm volatile("ldmatrix.sync.aligned.m8n8.x4.shared.b16 {%0,%1,%2,%3}, [%4];" \
        : "=r"((R)[0]), "=r"((R)[1]), "=r"((R)[2]), "=r"((R)[3]) : "r"(addr))

#define MMA16816(C, A, B0, B1) \
    asm volatile("mma.sync.aligned.m16n8k16.row.col.f32.bf16.bf16.f32 " \
        "{%0,%1,%2,%3}, {%4,%5,%6,%7}, {%8,%9}, {%0,%1,%2,%3};" \
        : "+f"((C)[0]), "+f"((C)[1]), "+f"((C)[2]), "+f"((C)[3]) \
        : "r"((A)[0]), "r"((A)[1]), "r"((A)[2]), "r"((A)[3]), "r"(B0), "r"(B1))

// swizzled byte offset inside a tile with 64B (32 bf16) rows
__device__ __forceinline__ uint32_t sw64(int r, int c) {
    return (uint32_t)(r * 64 + ((c ^ ((r >> 1) & 3)) << 4));
}

// ---------------- GEMM smem layout ----------------
#define S_AH 0
#define S_AL 8192
#define S_BH 16384
#define S_BL 24576
#define STAGE_SZ 32768
#define NSTAGE 4
#define GEMM_SMEM (NSTAGE * STAGE_SZ)   // 128 KB, 4-stage ring

// ---------------- small utility kernels ----------------
__global__ void edge_init_kernel(const int* __restrict__ ei) {
    int e = blockIdx.x * 256 + threadIdx.x;
    g_src[e] = ei[e];
    g_dst[e] = ei[E_TOT + e];
    g_valid[e] = 1;
}

__global__ void zero_cnt_kernel() {
    int i = blockIdx.x * 256 + threadIdx.x;
    if (i < NMAX) g_cnt[i] = 0;
}

__global__ void zero_out_kernel(float* out) {
    int i = blockIdx.x * 256 + threadIdx.x;
    out[i] = 0.0f;
}

__global__ void count_kernel() {
    int e = blockIdx.x * 256 + threadIdx.x;
    if (g_valid[e]) atomicAdd(&g_cnt[g_dst[e]], 1);
}

// single-block exclusive scan over g_cnt[0..n) -> g_rowptr / g_cursor
__global__ void scan_kernel(int n) {
    __shared__ int part[256];
    int tid = threadIdx.x;
    int chunk = (n + 255) >> 8;
    int base = tid * chunk;
    int s = 0;
    for (int i = 0; i < chunk; i++) { int idx = base + i; if (idx < n) s += g_cnt[idx]; }
    part[tid] = s;
    __syncthreads();
    for (int off = 1; off < 256; off <<= 1) {
        int v = (tid >= off) ? part[tid - off] : 0;
        __syncthreads();
        part[tid] += v;
        __syncthreads();
    }
    int run = part[tid] - s;  // exclusive prefix
    for (int i = 0; i < chunk; i++) {
        int idx = base + i;
        if (idx < n) { g_rowptr[idx] = run; g_cursor[idx] = run; run += g_cnt[idx]; }
    }
}

__global__ void scatter_kernel() {
    int e = blockIdx.x * 256 + threadIdx.x;
    if (g_valid[e]) {
        int pos = atomicAdd(&g_cursor[g_dst[e]], 1);
        g_csr[pos] = g_src[e];
    }
}

__device__ __forceinline__ void split_store(float v, __nv_bfloat16* hi, __nv_bfloat16* lo) {
    __nv_bfloat16 h = __float2bfloat16(v);
    *hi = h;
    *lo = __float2bfloat16(v - __bfloat162float(h));
}

// one block (256 threads) per dst node; NF = F/256. Writes bf16 hi/lo directly.
// 4-way edge unroll for memory-level parallelism.
template <int NF>
__global__ void aggregate_kernel(const float* __restrict__ xext, int sel, int F) {
    const float* __restrict__ xin = sel ? g_bufB : xext;
    int node = blockIdx.x;
    int c = g_cnt[node];
    int start = g_rowptr[node];
    float acc[NF];
#pragma unroll
    for (int i = 0; i < NF; i++) acc[i] = 0.0f;
    int e = 0;
    for (; e + 3 < c; e += 4) {
        const float* r0 = xin + (size_t)g_csr[start + e + 0] * F;
        const float* r1 = xin + (size_t)g_csr[start + e + 1] * F;
        const float* r2 = xin + (size_t)g_csr[start + e + 2] * F;
        const float* r3 = xin + (size_t)g_csr[start + e + 3] * F;
        float v0[NF], v1[NF], v2[NF], v3[NF];
#pragma unroll
        for (int i = 0; i < NF; i++) {
            int o = threadIdx.x + i * 256;
            v0[i] = r0[o]; v1[i] = r1[o]; v2[i] = r2[o]; v3[i] = r3[o];
        }
#pragma unroll
        for (int i = 0; i < NF; i++) acc[i] += (v0[i] + v1[i]) + (v2[i] + v3[i]);
    }
    for (; e < c; e++) {
        const float* row = xin + (size_t)g_csr[start + e] * F;
#pragma unroll
        for (int i = 0; i < NF; i++) acc[i] += row[threadIdx.x + i * 256];
    }
    float inv = 1.0f / (float)(c > 1 ? c : 1);
#pragma unroll
    for (int i = 0; i < NF; i++) {
        size_t o = (size_t)node * F + threadIdx.x + i * 256;
        split_store(acc[i] * inv, &g_ahi[o], &g_alo[o]);
    }
}

// fp32 -> bf16 hi/lo conversion (for x input and weights)
__global__ void conv_kernel(const float* __restrict__ src,
                            __nv_bfloat16* __restrict__ hi,
                            __nv_bfloat16* __restrict__ lo, int n) {
    int i = blockIdx.x * 256 + threadIdx.x;
    if (i < n) split_store(src[i], &hi[i], &lo[i]);
}

// ---------------- mma.sync fused SAGE GEMM ----------------
// g_bufA[M,1024] = relu( Agg @ Wl^T + bias + X @ Wr^T )
// 3-term bf16 split: Ah*Bh + Ah*Bl + Al*Bh, fp32 accum.
// CTA tile 128x128, BK=32, 8 warps (warp tile 32m x 64n), cp.async 4-stage ring.
// Term loop is OUTERMOST in the MMA schedule: 16 independent MMAs between any
// accumulator reuse (no HMMA RAW stalls).
__global__ void __launch_bounds__(256, 1)
gemm_mma_kernel(int M, int K, const float* __restrict__ bias) {
    extern __shared__ char smem[];
    const uint32_t sbase = smem_u32(smem);
    const int tid  = threadIdx.x;
    const int lane = tid & 31;
    const int warp = tid >> 5;
    const int warpM = (warp & 3) * 32;
    const int warpN = (warp >> 2) * 64;
    const int row0 = blockIdx.x << 7;
    const int col0 = blockIdx.y << 7;

    const int nchunk = K >> 5;       // k32 chunks per operand source
    const int ntot = nchunk << 1;

    float C[2][8][4];
#pragma unroll
    for (int a = 0; a < 2; a++)
#pragma unroll
        for (int b = 0; b < 8; b++)
#pragma unroll
            for (int d = 0; d < 4; d++) C[a][b][d] = 0.0f;

    // ---- stage prefetch (always commits exactly one group) ----
    auto prefetch = [&](int i) {
        if (i < ntot) {
            int src = (i >= nchunk) ? 1 : 0;
            int k0 = (i - (src ? nchunk : 0)) << 5;
            const __nv_bfloat16* Ah = src ? g_xhi : g_ahi;
            const __nv_bfloat16* Al = src ? g_xlo : g_alo;
            const __nv_bfloat16* Bh = g_whi + (size_t)src * HDIM * K;
            const __nv_bfloat16* Bl = g_wlo + (size_t)src * HDIM * K;
            uint32_t sb = sbase + (uint32_t)(i % NSTAGE) * STAGE_SZ;
#pragma unroll
            for (int u = 0; u < 2; u++) {
                int q = tid + (u << 8);
                int r = q >> 2, c = q & 3;
                uint32_t so = sw64(r, c);
                int gr = row0 + r;
                int ok = (gr < M) ? 16 : 0;
                size_t gro = (size_t)(ok ? gr : 0) * K + k0 + (c << 3);
                cpa16(sb + S_AH + so, Ah + gro, ok);
                cpa16(sb + S_AL + so, Al + gro, ok);
                size_t gco = (size_t)(col0 + r) * K + k0 + (c << 3);
                cpa16(sb + S_BH + so, Bh + gco, 16);
                cpa16(sb + S_BL + so, Bl + gco, 16);
            }
        }
        CP_COMMIT();
    };

    prefetch(0);
    prefetch(1);
    prefetch(2);

    for (int i = 0; i < ntot; i++) {
        CP_WAIT2();
        __syncthreads();
        prefetch(i + 3);

        uint32_t sb = sbase + (uint32_t)(i % NSTAGE) * STAGE_SZ;
#pragma unroll
        for (int kk = 0; kk < 2; kk++) {
            uint32_t ah[2][4], al[2][4];
#pragma unroll
            for (int fm = 0; fm < 2; fm++) {
                int r = warpM + fm * 16 + (lane & 15);
                int c = (kk << 1) + (lane >> 4);
                uint32_t so = sw64(r, c);
                LDSM_X4(ah[fm], sb + S_AH + so);
                LDSM_X4(al[fm], sb + S_AL + so);
            }
            uint32_t bh[4][4], bl[4][4];
#pragma unroll
            for (int fn = 0; fn < 4; fn++) {
                int r = warpN + fn * 16 + ((lane >> 4) << 3) + (lane & 7);
                int c = (kk << 1) + ((lane >> 3) & 1);
                uint32_t so = sw64(r, c);
                LDSM_X4(bh[fn], sb + S_BH + so);
                LDSM_X4(bl[fn], sb + S_BL + so);
            }
            // term-outer schedule: no accumulator RAW between adjacent MMAs
#pragma unroll
            for (int t = 0; t < 3; t++) {
#pragma unroll
                for (int fm = 0; fm < 2; fm++)
#pragma unroll
                    for (int fn = 0; fn < 4; fn++)
#pragma unroll
                        for (int g = 0; g < 2; g++) {
                            float* Cp = C[fm][fn * 2 + g];
                            const uint32_t* A = (t == 2) ? al[fm] : ah[fm];
                            const uint32_t* Bq = (t == 1) ? bl[fn] : bh[fn];
                            MMA16816(Cp, A, Bq[g * 2], Bq[g * 2 + 1]);
                        }
            }
        }
    }

    // ---- epilogue: bias + relu, direct stores ----
#pragma unroll
    for (int fm = 0; fm < 2; fm++)
#pragma unroll
        for (int fn = 0; fn < 4; fn++)
#pragma unroll
            for (int g = 0; g < 2; g++) {
                int rb = row0 + warpM + fm * 16 + (lane >> 2);
                int col = col0 + warpN + fn * 16 + g * 8 + ((lane & 3) << 1);
                float2 bb = *(const float2*)(bias + col);
                float* Cp = C[fm][fn * 2 + g];
                if (rb < M) {
                    float2 v;
                    v.x = fmaxf(Cp[0] + bb.x, 0.0f);
                    v.y = fmaxf(Cp[1] + bb.y, 0.0f);
                    *(float2*)(g_bufA + (size_t)rb * HDIM + col) = v;
                }
                if (rb + 8 < M) {
                    float2 v;
                    v.x = fmaxf(Cp[2] + bb.x, 0.0f);
                    v.y = fmaxf(Cp[3] + bb.y, 0.0f);
                    *(float2*)(g_bufA + (size_t)(rb + 8) * HDIM + col) = v;
                }
            }
}

// ---------------- scoring / top-k / pooling ----------------
__global__ void pnorm_kernel(const float* __restrict__ p) {
    __shared__ float sh[256];
    float s = 0.0f;
    for (int i = threadIdx.x; i < HDIM; i += 256) s += p[i] * p[i];
    sh[threadIdx.x] = s;
    __syncthreads();
    for (int o = 128; o; o >>= 1) {
        if (threadIdx.x < o) sh[threadIdx.x] += sh[threadIdx.x + o];
        __syncthreads();
    }
    if (threadIdx.x == 0) g_pnorm = sqrtf(sh[0]);
}

// one warp per node: s = tanh((h . p)/||p||)
__global__ void score_kernel(const float* __restrict__ p, int N) {
    int t = blockIdx.x * blockDim.x + threadIdx.x;
    int warp = t >> 5, lane = t & 31;
    if (warp >= N) return;
    const float* row = g_bufA + (size_t)warp * HDIM;
    float acc = 0.0f;
#pragma unroll 8
    for (int i = lane; i < HDIM; i += 32) acc += row[i] * p[i];
#pragma unroll
    for (int o = 16; o; o >>= 1) acc += __shfl_xor_sync(0xffffffffu, acc, o);
    if (lane == 0) g_score[warp] = tanhf(acc / g_pnorm);
}

// one block per graph: bitonic sort 1024 (score,idx) pairs descending
__global__ void topk_kernel(int n_per, int k) {
    __shared__ float ss[1024];
    __shared__ int si[1024];
    int g = blockIdx.x;
    int tid = threadIdx.x;  // 512 threads
    for (int i = tid; i < 1024; i += 512) {
        if (i < n_per) { ss[i] = g_score[g * n_per + i]; si[i] = i; }
        else           { ss[i] = -FLT_MAX;               si[i] = i; }
    }
    __syncthreads();
    for (int ksz = 2; ksz <= 1024; ksz <<= 1) {
        for (int j = ksz >> 1; j > 0; j >>= 1) {
            for (int i = tid; i < 1024; i += 512) {
                int ixj = i ^ j;
                if (ixj > i) {
                    bool dirDesc = ((i & ksz) == 0);
                    float a = ss[i], b = ss[ixj];
                    bool doswap = dirDesc ? (a < b) : (a > b);
                    if (doswap) {
                        ss[i] = b; ss[ixj] = a;
                        int tpi = si[i]; si[i] = si[ixj]; si[ixj] = tpi;
                    }
                }
            }
            __syncthreads();
        }
    }
    for (int r = tid; r < n_per; r += 512) {
        int oldLocal = si[r];
        if (r < k) {
            g_old[g * k + r]  = g * n_per + oldLocal;
            g_vals[g * k + r] = ss[r];
            g_remap[g * n_per + oldLocal] = g * k + r;
        } else {
            g_remap[g * n_per + oldLocal] = -1;
        }
    }
}

// new node i <- old node * score; also emit bf16 hi/lo for the next layer GEMM
__global__ void gate_kernel() {
    int i = blockIdx.x;
    int old = g_old[i];
    float v = g_vals[i];
    const float* srcp = g_bufA + (size_t)old * HDIM;
    float* dstp = g_bufB + (size_t)i * HDIM;
    for (int f = threadIdx.x; f < HDIM; f += 256) {
        float val = srcp[f] * v;
        dstp[f] = val;
        split_store(val, &g_xhi[(size_t)i * HDIM + f], &g_xlo[(size_t)i * HDIM + f]);
    }
}

__global__ void edge_remap_kernel() {
    int e = blockIdx.x * 256 + threadIdx.x;
    if (!g_valid[e]) return;
    int s2 = g_remap[g_src[e]];
    int d2 = g_remap[g_dst[e]];
    if (s2 >= 0 && d2 >= 0) { g_src[e] = s2; g_dst[e] = d2; }
    else g_valid[e] = 0;
}

// out[g, 0:1024] += col-max, out[g, 1024:2048] += col-mean   (over bufB)
__global__ void readout_kernel(float* __restrict__ out, int nper) {
    int gid = blockIdx.x * 256 + threadIdx.x;  // < B*1024
    int g = gid >> 10, f = gid & 1023;
    const float* base = g_bufB + (size_t)g * nper * HDIM + f;
    float mx = -FLT_MAX, sm = 0.0f;
    for (int i = 0; i < nper; i++) {
        float v = base[(size_t)i * HDIM];
        mx = fmaxf(mx, v);
        sm += v;
    }
    out[g * 2048 + f] += mx;
    out[g * 2048 + 1024 + f] += sm / (float)nper;
}

// ---------------- host orchestration ----------------
static void build_csr(int n_nodes) {
    zero_cnt_kernel<<<NMAX / 256, 256>>>();
    count_kernel<<<E_TOT / 256, 256>>>();
    scan_kernel<<<1, 256>>>(n_nodes);
    scatter_kernel<<<E_TOT / 256, 256>>>();
}

static void launch_gemm(int M, int K, const float* bias) {
    dim3 grid((M + 127) >> 7, HDIM / 128);
    gemm_mma_kernel<<<grid, 256, GEMM_SMEM>>>(M, K, bias);
}

extern "C" void kernel_launch(void* const* d_in, const int* in_sizes, int n_in,
                              void* d_out, int out_size) {
    const float* x  = (const float*)d_in[0];
    const int*   ei = (const int*)d_in[1];
    const float* W1l = (const float*)d_in[3];
    const float* b1  = (const float*)d_in[4];
    const float* W1r = (const float*)d_in[5];
    const float* p1  = (const float*)d_in[6];
    const float* W2l = (const float*)d_in[7];
    const float* b2  = (const float*)d_in[8];
    const float* W2r = (const float*)d_in[9];
    const float* p2  = (const float*)d_in[10];
    const float* W3l = (const float*)d_in[11];
    const float* b3  = (const float*)d_in[12];
    const float* W3r = (const float*)d_in[13];
    const float* p3  = (const float*)d_in[14];
    float* out = (float*)d_out;

    static int s_attr_done = 0;
    if (!s_attr_done) {
        cudaFuncSetAttribute(gemm_mma_kernel,
                             cudaFuncAttributeMaxDynamicSharedMemorySize, GEMM_SMEM);
        s_attr_done = 1;
    }

    const int N1 = B_GR * NP_;   // 16384
    const int N2 = B_GR * K1_;   // 13120
    const int N3 = B_GR * K2_;   // 10496

    __nv_bfloat16 *whi = nullptr, *wlo = nullptr;
    cudaGetSymbolAddress((void**)&whi, g_whi);
    cudaGetSymbolAddress((void**)&wlo, g_wlo);
    __nv_bfloat16 *xhi = nullptr, *xlo = nullptr;
    cudaGetSymbolAddress((void**)&xhi, g_xhi);
    cudaGetSymbolAddress((void**)&xlo, g_xlo);

    edge_init_kernel<<<E_TOT / 256, 256>>>(ei);
    zero_out_kernel<<<(B_GR * 2 * HDIM) / 256, 256>>>(out);

    // ---------- layer 1 (K = 512) ----------
    build_csr(N1);
    aggregate_kernel<2><<<N1, 256>>>(x, 0, FEAT_);
    conv_kernel<<<(N1 * FEAT_) / 256, 256>>>(x, xhi, xlo, N1 * FEAT_);
    conv_kernel<<<(HDIM * FEAT_) / 256, 256>>>(W1l, whi, wlo, HDIM * FEAT_);
    conv_kernel<<<(HDIM * FEAT_) / 256, 256>>>(W1r, whi + HDIM * FEAT_, wlo + HDIM * FEAT_,
                                               HDIM * FEAT_);
    launch_gemm(N1, FEAT_, b1);
    pnorm_kernel<<<1, 256>>>(p1);
    score_kernel<<<N1 / 8, 256>>>(p1, N1);
    topk_kernel<<<B_GR, 512>>>(NP_, K1_);
    gate_kernel<<<N2, 256>>>();
    edge_remap_kernel<<<E_TOT / 256, 256>>>();
    readout_kernel<<<(B_GR * HDIM) / 256, 256>>>(out, K1_);

    // ---------- layer 2 (K = 1024) ----------
    build_csr(N2);
    aggregate_kernel<4><<<N2, 256>>>(nullptr, 1, HDIM);
    conv_kernel<<<(HDIM * HDIM) / 256, 256>>>(W2l, whi, wlo, HDIM * HDIM);
    conv_kernel<<<(HDIM * HDIM) / 256, 256>>>(W2r, whi + HDIM * HDIM, wlo + HDIM * HDIM,
                                              HDIM * HDIM);
    launch_gemm(N2, HDIM, b2);
    pnorm_kernel<<<1, 256>>>(p2);
    score_kernel<<<N2 / 8, 256>>>(p2, N2);
    topk_kernel<<<B_GR, 512>>>(K1_, K2_);
    gate_kernel<<<N3, 256>>>();
    edge_remap_kernel<<<E_TOT / 256, 256>>>();
    readout_kernel<<<(B_GR * HDIM) / 256, 256>>>(out, K2_);

    // ---------- layer 3 (K = 1024) ----------
    build_csr(N3);
    aggregate_kernel<4><<<N3, 256>>>(nullptr, 1, HDIM);
    conv_kernel<<<(HDIM * HDIM) / 256, 256>>>(W3l, whi, wlo, HDIM * HDIM);
    conv_kernel<<<(HDIM * HDIM) / 256, 256>>>(W3r, whi + HDIM * HDIM, wlo + HDIM * HDIM,
                                              HDIM * HDIM);
    launch_gemm(N3, HDIM, b3);
    pnorm_kernel<<<1, 256>>>(p3);
    score_kernel<<<N3 / 8, 256>>>(p3, N3);
    topk_kernel<<<B_GR, 512>>>(K2_, K3_);
    gate_kernel<<<B_GR * K3_, 256>>>();
    readout_kernel<<<(B_GR * HDIM) / 256, 256>>>(out, K3_);
}